// round 14
// baseline (speedup 1.0000x reference)
#include <cuda_runtime.h>
#include <cuda_bf16.h>

#define N_ 384
#define D_ 256
#define H_ 8
#define DH_ 32
#define SCALE_ 0.17677669529663687f
#define L2E_ 1.4426950408889634f

typedef unsigned long long u64;

// ---------------- scratch (device globals; no allocation allowed) ----------
__device__ __align__(16) float g_Q [N_*H_*DH_];
__device__ __align__(16) float g_K [N_*H_*DH_];
__device__ __align__(16) float g_V [N_*H_*DH_];
__device__ __align__(16) float g_KQ[N_*H_*D_];   // [n][h][d] scale folded
__device__ __align__(16) float g_CK[N_*H_*D_];   // [n][h][d] scale folded
__device__ __align__(16) float g_PV[N_*H_*D_];   // [n][h][c]
__device__ __align__(16) float g_CB[N_*H_];
__device__ __align__(16) float g_SB[N_*H_];
__device__ __align__(16) float g_SI[(size_t)N_*N_*H_];   // [i][j][h]
__device__ __align__(16) float g_AI[(size_t)N_*N_*H_];   // [j][i][h]  (transposed!)
__device__ __align__(16) float g_AJ[(size_t)N_*N_*H_];   // [j][i][h]

// ---------------- packed f32x2 helpers -------------------------------------
union F2U { float2 f; u64 u; };

__device__ __forceinline__ void dfma2(u64 &d, u64 a, u64 b) {
    asm("fma.rn.f32x2 %0, %1, %2, %0;" : "+l"(d) : "l"(a), "l"(b));
}
__device__ __forceinline__ u64 bcast2(float v) {
    F2U t; t.f.x = v; t.f.y = v; return t.u;
}
__device__ __forceinline__ float hsum2(u64 a) {
    F2U t; t.u = a; return t.f.x + t.f.y;
}
__device__ __forceinline__ u64 pack2f(float a, float b) {
    F2U t; t.f.x = a; t.f.y = b; return t.u;
}

// ---------------- P1: qx/kx/vx + cb/sb -------------------------------------
__global__ void kP1(const float* __restrict__ x,
                    const float* __restrict__ Wq_x, const float* __restrict__ bq_x,
                    const float* __restrict__ Wk_x, const float* __restrict__ bk_x,
                    const float* __restrict__ Wv_x, const float* __restrict__ bv_x,
                    const float* __restrict__ bk_e, const float* __restrict__ bq_e)
{
    __shared__ float x_s[8][D_];
    __shared__ float q_s[8][H_][DH_];
    __shared__ float k_s[8][H_][DH_];
    __shared__ float v_s[8][H_][DH_];
    const int t  = threadIdx.x;
    const int n0 = blockIdx.x * 8;

    #pragma unroll
    for (int n = 0; n < 8; n++) x_s[n][t] = x[(n0 + n) * D_ + t];
    __syncthreads();

    {
        const int h = t >> 5, k = t & 31;
        float aq[8], ak[8], av[8];
        const float bq = bq_x[h*DH_ + k], bk = bk_x[h*DH_ + k], bv = bv_x[h*DH_ + k];
        #pragma unroll
        for (int n = 0; n < 8; n++) { aq[n] = bq; ak[n] = bk; av[n] = bv; }
        for (int d = 0; d < D_; d++) {
            const float wq = Wq_x[(h*D_ + d)*DH_ + k];
            const float wk = Wk_x[(h*D_ + d)*DH_ + k];
            const float wv = Wv_x[(h*D_ + d)*DH_ + k];
            #pragma unroll
            for (int n = 0; n < 8; n++) {
                const float xv = x_s[n][d];
                aq[n] += xv * wq; ak[n] += xv * wk; av[n] += xv * wv;
            }
        }
        #pragma unroll
        for (int n = 0; n < 8; n++) {
            q_s[n][h][k] = aq[n]; k_s[n][h][k] = ak[n]; v_s[n][h][k] = av[n];
        }
    }
    __syncthreads();

    if (t < 64) {
        const int n = t >> 3, hh = t & 7;
        float cb = 0.f, sb = 0.f;
        #pragma unroll
        for (int kk = 0; kk < DH_; kk++) {
            cb += q_s[n][hh][kk] * bk_e[hh*DH_ + kk];
            sb += k_s[n][hh][kk] * bq_e[hh*DH_ + kk];
        }
        g_CB[(n0 + n)*H_ + hh] = cb * SCALE_;
        g_SB[(n0 + n)*H_ + hh] = sb * SCALE_;
    }

    const float* qs = (const float*)q_s;
    const float* ks = (const float*)k_s;
    const float* vs = (const float*)v_s;
    for (int idx = t; idx < 2048; idx += 256) {
        g_Q[n0*256 + idx] = qs[idx];
        g_K[n0*256 + idx] = ks[idx];
        g_V[n0*256 + idx] = vs[idx];
    }
}

// ---------------- P2: kq, ck, pv (smem-staged weights, conflict-free) -------
__global__ void __launch_bounds__(256) kP2(const float* __restrict__ Wk_e,
                                           const float* __restrict__ Wq_e,
                                           const float* __restrict__ WOe)
{
    __shared__ float w_s[256][33];
    __shared__ float q8[8][DH_], k8[8][DH_], v8[8][DH_];
    const int n0 = blockIdx.x * 8;
    const int hh = blockIdx.y;
    const int t  = threadIdx.x;

    {
        const int n = t >> 5, k = t & 31;
        q8[n][k] = g_Q[((n0 + n)*H_ + hh)*DH_ + k];
        k8[n][k] = g_K[((n0 + n)*H_ + hh)*DH_ + k];
        v8[n][k] = g_V[((n0 + n)*H_ + hh)*DH_ + k];
    }
    for (int idx = t; idx < 8192; idx += 256)
        w_s[idx >> 5][idx & 31] = Wk_e[hh*8192 + idx];
    __syncthreads();

    float akq[8], apv[8];
    #pragma unroll
    for (int n = 0; n < 8; n++) { akq[n] = 0.f; apv[n] = 0.f; }
    #pragma unroll 4
    for (int k = 0; k < DH_; k++) {
        const float wk = w_s[t][k];
        const float wo = WOe[(hh*DH_ + k)*D_ + t];
        #pragma unroll
        for (int n = 0; n < 8; n++) { akq[n] += wk * q8[n][k]; apv[n] += wo * v8[n][k]; }
    }
    __syncthreads();
    for (int idx = t; idx < 8192; idx += 256)
        w_s[idx >> 5][idx & 31] = Wq_e[hh*8192 + idx];
    __syncthreads();

    float ack[8];
    #pragma unroll
    for (int n = 0; n < 8; n++) ack[n] = 0.f;
    #pragma unroll 4
    for (int k = 0; k < DH_; k++) {
        const float wq = w_s[t][k];
        #pragma unroll
        for (int n = 0; n < 8; n++) ack[n] += wq * k8[n][k];
    }
    #pragma unroll
    for (int n = 0; n < 8; n++) {
        const int base = ((n0 + n)*H_ + hh)*D_ + t;
        g_KQ[base] = akq[n] * SCALE_;
        g_CK[base] = ack[n] * SCALE_;
        g_PV[base] = apv[n];
    }
}

// ---------------- S: row pass (8-lane segments) + we + x projections --------
// Block = row i, 384 thr = 12 warps x 4 edges x 8 lanes.
// Phase 1: s_en p + s_i (coalesced e, smem-broadcast operands, 3-round reduce)
// Phase 3: we accumulation re-reading the row (L2-hit). Phase 4: x_out.
__global__ void __launch_bounds__(384) kS(const float* __restrict__ e,
                                          const float* __restrict__ Wv_e,
                                          const float* __restrict__ bv_e,
                                          const float* __restrict__ WOx,
                                          const float* __restrict__ bOx,
                                          float* __restrict__ xout)
{
    __shared__ __align__(16) float kq_s[H_*D_];     // 8 KB
    __shared__ __align__(16) float ck_s[H_*D_];     // 8 KB
    __shared__ __align__(16) float p_s[N_][H_];     // 12 KB
    __shared__ __align__(16) float lsp[48][H_];     // 1.5 KB
    __shared__ float ls_s[H_];
    __shared__ float we_s[H_][D_];                  // 8 KB
    __shared__ float xh_s[D_];
    const int i = blockIdx.x;
    const int t = threadIdx.x;
    const int w = t >> 5, l = t & 31;
    const int es = l >> 3, cl = l & 7;              // edge-sub, channel-lane
    const int widx = w*4 + es;                      // 0..47

    for (int idx = t; idx < H_*D_; idx += 384) {
        kq_s[idx] = g_KQ[i*H_*D_ + idx];
        ck_s[idx] = g_CK[i*H_*D_ + idx];
    }
    __syncthreads();

    float cb[8], sb[8];
    {
        const float4 cA = *(const float4*)(g_CB + i*H_);
        const float4 cB = *(const float4*)(g_CB + i*H_ + 4);
        const float4 sA = *(const float4*)(g_SB + i*H_);
        const float4 sB = *(const float4*)(g_SB + i*H_ + 4);
        cb[0]=cA.x; cb[1]=cA.y; cb[2]=cA.z; cb[3]=cA.w;
        cb[4]=cB.x; cb[5]=cB.y; cb[6]=cB.z; cb[7]=cB.w;
        sb[0]=sA.x; sb[1]=sA.y; sb[2]=sA.z; sb[3]=sA.w;
        sb[4]=sB.x; sb[5]=sB.y; sb[6]=sB.z; sb[7]=sB.w;
    }
    float lsum[8];
    #pragma unroll
    for (int h = 0; h < 8; h++) lsum[h] = 0.f;

    const float* ebase = e + (size_t)i*N_*D_;

    #pragma unroll 1
    for (int it = 0; it < 8; it++) {
        const int j = it*48 + widx;
        u64 aq[8], as[8];
        #pragma unroll
        for (int h = 0; h < 8; h++) { aq[h] = 0ull; as[h] = 0ull; }

        #pragma unroll
        for (int c = 0; c < 8; c++) {
            const float4 ev4 = *(const float4*)(ebase + (size_t)j*D_ + c*32 + cl*4);
            const u64 e0 = pack2f(ev4.x, ev4.y), e1 = pack2f(ev4.z, ev4.w);
            #pragma unroll
            for (int h = 0; h < 8; h++) {
                const float4 kv = *(const float4*)&kq_s[h*D_ + c*32 + cl*4];
                const float4 cv = *(const float4*)&ck_s[h*D_ + c*32 + cl*4];
                dfma2(aq[h], e0, pack2f(kv.x, kv.y));
                dfma2(aq[h], e1, pack2f(kv.z, kv.w));
                dfma2(as[h], e0, pack2f(cv.x, cv.y));
                dfma2(as[h], e1, pack2f(cv.z, cv.w));
            }
        }
        float dq[8], ds[8];
        #pragma unroll
        for (int h = 0; h < 8; h++) { dq[h] = hsum2(aq[h]); ds[h] = hsum2(as[h]); }
        #pragma unroll
        for (int o = 4; o; o >>= 1) {       // segmented reduce within 8 lanes
            #pragma unroll
            for (int h = 0; h < 8; h++) {
                dq[h] += __shfl_xor_sync(0xffffffffu, dq[h], o);
                ds[h] += __shfl_xor_sync(0xffffffffu, ds[h], o);
            }
        }
        if (cl == 0) {
            float4* sip = (float4*)(g_SI + ((size_t)i*N_ + j)*H_);
            sip[0] = make_float4(ds[0]+sb[0], ds[1]+sb[1], ds[2]+sb[2], ds[3]+sb[3]);
            sip[1] = make_float4(ds[4]+sb[4], ds[5]+sb[5], ds[6]+sb[6], ds[7]+sb[7]);
            // scores O(+-5): exp2 cannot overflow; softmax shift-invariant.
            float p[8];
            #pragma unroll
            for (int h = 0; h < 8; h++) { p[h] = exp2f((dq[h]+cb[h])*L2E_); lsum[h] += p[h]; }
            *(float4*)&p_s[j][0] = make_float4(p[0], p[1], p[2], p[3]);
            *(float4*)&p_s[j][4] = make_float4(p[4], p[5], p[6], p[7]);
        }
    }
    if (cl == 0) {
        *(float4*)&lsp[widx][0] = make_float4(lsum[0], lsum[1], lsum[2], lsum[3]);
        *(float4*)&lsp[widx][4] = make_float4(lsum[4], lsum[5], lsum[6], lsum[7]);
    }
    __syncthreads();
    if (t < 8) {
        float s = 0.f;
        for (int q = 0; q < 48; q++) s += lsp[q][t];
        ls_s[t] = s;
    }
    __syncthreads();

    // Phase 3: we[h][ch] = sum_j p[j][h] * e[i][j][ch]   (row re-read: L2 hit)
    if (t < D_) {
        float we[8];
        #pragma unroll
        for (int h = 0; h < 8; h++) we[h] = 0.f;
        const float* erow = ebase + t;
        #pragma unroll 4
        for (int j = 0; j < N_; j++) {
            const float ev = erow[(size_t)j*D_];
            const float4 pA = *(const float4*)&p_s[j][0];
            const float4 pB = *(const float4*)&p_s[j][4];
            we[0] += pA.x*ev; we[1] += pA.y*ev; we[2] += pA.z*ev; we[3] += pA.w*ev;
            we[4] += pB.x*ev; we[5] += pB.y*ev; we[6] += pB.z*ev; we[7] += pB.w*ev;
        }
        #pragma unroll
        for (int h = 0; h < 8; h++)
            we_s[h][t] = we[h] * __fdividef(1.f, ls_s[h]);
    }
    __syncthreads();

    // Phase 4: x projections
    if (t < D_) {
        const int h = t >> 5, k = t & 31;
        float acc = bv_e[h*DH_ + k];
        #pragma unroll 4
        for (int d = 0; d < D_; d++)
            acc += we_s[h][d] * Wv_e[(h*D_ + d)*DH_ + k];
        xh_s[t] = acc;
    }
    __syncthreads();
    if (t < D_) {
        float o = bOx[t];
        #pragma unroll 4
        for (int u = 0; u < D_; u++)
            o += xh_s[u] * WOx[u*D_ + t];
        xout[i*D_ + t] = o;
    }
}

// ---------------- T: column pass (8-lane segments) -> ai/aj -----------------
// Block = col j, 384 thr = 12 warps x 4 edges x 8 lanes.
__global__ void __launch_bounds__(384) kT(const float* __restrict__ e)
{
    __shared__ __align__(16) float ck_s[H_*D_];     // 8 KB
    const int j = blockIdx.x;
    const int t = threadIdx.x;
    const int w = t >> 5, l = t & 31;
    const int es = l >> 3, cl = l & 7;
    const int widx = w*4 + es;

    for (int idx = t; idx < H_*D_; idx += 384)
        ck_s[idx] = g_CK[j*H_*D_ + idx];
    __syncthreads();

    float sb[8];
    {
        const float4 sA = *(const float4*)(g_SB + j*H_);
        const float4 sB = *(const float4*)(g_SB + j*H_ + 4);
        sb[0]=sA.x; sb[1]=sA.y; sb[2]=sA.z; sb[3]=sA.w;
        sb[4]=sB.x; sb[5]=sB.y; sb[6]=sB.z; sb[7]=sB.w;
    }

    #pragma unroll 1
    for (int it = 0; it < 8; it++) {
        const int i = it*48 + widx;
        u64 as[8];
        #pragma unroll
        for (int h = 0; h < 8; h++) as[h] = 0ull;

        #pragma unroll
        for (int c = 0; c < 8; c++) {
            const float4 ev4 = *(const float4*)(e + ((size_t)i*N_ + j)*D_ + c*32 + cl*4);
            const u64 e0 = pack2f(ev4.x, ev4.y), e1 = pack2f(ev4.z, ev4.w);
            #pragma unroll
            for (int h = 0; h < 8; h++) {
                const float4 cv = *(const float4*)&ck_s[h*D_ + c*32 + cl*4];
                dfma2(as[h], e0, pack2f(cv.x, cv.y));
                dfma2(as[h], e1, pack2f(cv.z, cv.w));
            }
        }
        float ds[8];
        #pragma unroll
        for (int h = 0; h < 8; h++) ds[h] = hsum2(as[h]);
        #pragma unroll
        for (int o = 4; o; o >>= 1) {
            #pragma unroll
            for (int h = 0; h < 8; h++)
                ds[h] += __shfl_xor_sync(0xffffffffu, ds[h], o);
        }
        if (cl == 0) {
            const float4 sA = *(const float4*)(g_SI + ((size_t)i*N_ + j)*H_);
            const float4 sB = *(const float4*)(g_SI + ((size_t)i*N_ + j)*H_ + 4);
            const float si[8] = {sA.x, sA.y, sA.z, sA.w, sB.x, sB.y, sB.z, sB.w};
            float ai[8], aj[8];
            #pragma unroll
            for (int h = 0; h < 8; h++) {
                // ai = 1/(1+exp(sj-si)); aj = 1-ai (sigmoid form of 2-way softmax)
                const float xval = exp2f((ds[h] + sb[h] - si[h]) * L2E_);
                ai[h] = __fdividef(1.f, 1.f + xval);
                aj[h] = 1.f - ai[h];
            }
            float4* aip = (float4*)(g_AI + ((size_t)j*N_ + i)*H_);
            aip[0] = make_float4(ai[0], ai[1], ai[2], ai[3]);
            aip[1] = make_float4(ai[4], ai[5], ai[6], ai[7]);
            float4* ajp = (float4*)(g_AJ + ((size_t)j*N_ + i)*H_);
            ajp[0] = make_float4(aj[0], aj[1], aj[2], aj[3]);
            ajp[1] = make_float4(aj[4], aj[5], aj[6], aj[7]);
        }
    }
}

// ---------------- E: eout = sum_h ai*pv_i + aj*pv_j + bOe -------------------
__global__ void __launch_bounds__(256) kE(const float* __restrict__ bOe,
                                          float* __restrict__ eout)
{
    const int i0 = blockIdx.x * 8;
    const int t  = threadIdx.x;
    const int tt = t & 127, ih = t >> 7;
    const int cp = 2 * tt;

    u64 pvi[4][H_];
    #pragma unroll
    for (int q = 0; q < 4; q++)
        #pragma unroll
        for (int h = 0; h < H_; h++)
            pvi[q][h] = *(const u64*)(g_PV + ((size_t)(i0 + ih*4 + q)*H_ + h)*D_ + cp);
    const u64 bo = *(const u64*)(bOe + cp);

    const int j0 = blockIdx.y * 96;
    for (int j = j0; j < j0 + 96; j++) {
        u64 pvj[H_];
        #pragma unroll
        for (int h = 0; h < H_; h++)
            pvj[h] = *(const u64*)(g_PV + ((size_t)j*H_ + h)*D_ + cp);
        #pragma unroll
        for (int q = 0; q < 4; q++) {
            const int irow = i0 + ih*4 + q;
            const float4 aiA = *(const float4*)(g_AI + ((size_t)j*N_ + irow)*H_);
            const float4 aiB = *(const float4*)(g_AI + ((size_t)j*N_ + irow)*H_ + 4);
            const float4 ajA = *(const float4*)(g_AJ + ((size_t)j*N_ + irow)*H_);
            const float4 ajB = *(const float4*)(g_AJ + ((size_t)j*N_ + irow)*H_ + 4);
            const float ai8[8] = {aiA.x, aiA.y, aiA.z, aiA.w, aiB.x, aiB.y, aiB.z, aiB.w};
            const float aj8[8] = {ajA.x, ajA.y, ajA.z, ajA.w, ajB.x, ajB.y, ajB.z, ajB.w};
            u64 acc = bo;
            #pragma unroll
            for (int h = 0; h < H_; h++) {
                dfma2(acc, bcast2(ai8[h]), pvi[q][h]);
                dfma2(acc, bcast2(aj8[h]), pvj[h]);
            }
            *(u64*)(eout + ((size_t)irow*N_ + j)*D_ + cp) = acc;
        }
    }
}

// ---------------- launcher ---------------------------------------------------
extern "C" void kernel_launch(void* const* d_in, const int* in_sizes, int n_in,
                              void* d_out, int out_size)
{
    const float* x    = (const float*)d_in[0];
    const float* e    = (const float*)d_in[1];
    const float* Wq_x = (const float*)d_in[2];
    const float* bq_x = (const float*)d_in[3];
    const float* Wk_e = (const float*)d_in[4];
    const float* bk_e = (const float*)d_in[5];
    const float* Wv_e = (const float*)d_in[6];
    const float* bv_e = (const float*)d_in[7];
    const float* Wq_e = (const float*)d_in[8];
    const float* bq_e = (const float*)d_in[9];
    const float* Wk_x = (const float*)d_in[10];
    const float* bk_x = (const float*)d_in[11];
    const float* Wv_x = (const float*)d_in[12];
    const float* bv_x = (const float*)d_in[13];
    const float* WOx  = (const float*)d_in[14];
    const float* bOx  = (const float*)d_in[15];
    const float* WOe  = (const float*)d_in[16];
    const float* bOe  = (const float*)d_in[17];

    float* xout = (float*)d_out;                 // [384,256]
    float* eout = (float*)d_out + N_*D_;         // [384,384,256]

    kP1<<<48, 256>>>(x, Wq_x, bq_x, Wk_x, bk_x, Wv_x, bv_x, bk_e, bq_e);
    kP2<<<dim3(48, 8), 256>>>(Wk_e, Wq_e, WOe);
    kS <<<N_, 384>>>(e, Wv_e, bv_e, WOx, bOx, xout);
    kT <<<N_, 384>>>(e);
    kE <<<dim3(48, 4), 256>>>(bOe, eout);
}

// round 15
// speedup vs baseline: 2.2402x; 2.2402x over previous
#include <cuda_runtime.h>
#include <cuda_bf16.h>

#define N_ 384
#define D_ 256
#define H_ 8
#define DH_ 32
#define SCALE_ 0.17677669529663687f
#define L2E_ 1.4426950408889634f

typedef unsigned long long u64;

// ---------------- scratch (device globals; no allocation allowed) ----------
__device__ __align__(16) float g_Q [N_*H_*DH_];
__device__ __align__(16) float g_K [N_*H_*DH_];
__device__ __align__(16) float g_V [N_*H_*DH_];
__device__ __align__(16) float g_KQ[N_*H_*D_];   // [n][h][d] scale folded
__device__ __align__(16) float g_CK[N_*H_*D_];   // [n][h][d] scale folded
__device__ __align__(16) float g_PV[N_*H_*D_];   // [n][h][c]
__device__ __align__(16) float g_CB[N_*H_];
__device__ __align__(16) float g_SB[N_*H_];
__device__ __align__(16) float g_SI[(size_t)N_*N_*H_];   // [i][j][h]
__device__ __align__(16) float g_AI[(size_t)N_*N_*H_];   // [j][i][h]  (transposed!)
__device__ __align__(16) float g_AJ[(size_t)N_*N_*H_];   // [j][i][h]

// ---------------- packed f32x2 helpers -------------------------------------
union F2U { float2 f; u64 u; };

__device__ __forceinline__ void dfma2(u64 &d, u64 a, u64 b) {
    asm("fma.rn.f32x2 %0, %1, %2, %0;" : "+l"(d) : "l"(a), "l"(b));
}
__device__ __forceinline__ u64 bcast2(float v) {
    F2U t; t.f.x = v; t.f.y = v; return t.u;
}
__device__ __forceinline__ float hsum2(u64 a) {
    F2U t; t.u = a; return t.f.x + t.f.y;
}
__device__ __forceinline__ u64 pack2f(float a, float b) {
    F2U t; t.f.x = a; t.f.y = b; return t.u;
}

// ---------------- P1: qx/kx/vx + cb/sb -------------------------------------
__global__ void kP1(const float* __restrict__ x,
                    const float* __restrict__ Wq_x, const float* __restrict__ bq_x,
                    const float* __restrict__ Wk_x, const float* __restrict__ bk_x,
                    const float* __restrict__ Wv_x, const float* __restrict__ bv_x,
                    const float* __restrict__ bk_e, const float* __restrict__ bq_e)
{
    __shared__ float x_s[8][D_];
    __shared__ float q_s[8][H_][DH_];
    __shared__ float k_s[8][H_][DH_];
    __shared__ float v_s[8][H_][DH_];
    const int t  = threadIdx.x;
    const int n0 = blockIdx.x * 8;

    #pragma unroll
    for (int n = 0; n < 8; n++) x_s[n][t] = x[(n0 + n) * D_ + t];
    __syncthreads();

    {
        const int h = t >> 5, k = t & 31;
        float aq[8], ak[8], av[8];
        const float bq = bq_x[h*DH_ + k], bk = bk_x[h*DH_ + k], bv = bv_x[h*DH_ + k];
        #pragma unroll
        for (int n = 0; n < 8; n++) { aq[n] = bq; ak[n] = bk; av[n] = bv; }
        for (int d = 0; d < D_; d++) {
            const float wq = Wq_x[(h*D_ + d)*DH_ + k];
            const float wk = Wk_x[(h*D_ + d)*DH_ + k];
            const float wv = Wv_x[(h*D_ + d)*DH_ + k];
            #pragma unroll
            for (int n = 0; n < 8; n++) {
                const float xv = x_s[n][d];
                aq[n] += xv * wq; ak[n] += xv * wk; av[n] += xv * wv;
            }
        }
        #pragma unroll
        for (int n = 0; n < 8; n++) {
            q_s[n][h][k] = aq[n]; k_s[n][h][k] = ak[n]; v_s[n][h][k] = av[n];
        }
    }
    __syncthreads();

    if (t < 64) {
        const int n = t >> 3, hh = t & 7;
        float cb = 0.f, sb = 0.f;
        #pragma unroll
        for (int kk = 0; kk < DH_; kk++) {
            cb += q_s[n][hh][kk] * bk_e[hh*DH_ + kk];
            sb += k_s[n][hh][kk] * bq_e[hh*DH_ + kk];
        }
        g_CB[(n0 + n)*H_ + hh] = cb * SCALE_;
        g_SB[(n0 + n)*H_ + hh] = sb * SCALE_;
    }

    const float* qs = (const float*)q_s;
    const float* ks = (const float*)k_s;
    const float* vs = (const float*)v_s;
    for (int idx = t; idx < 2048; idx += 256) {
        g_Q[n0*256 + idx] = qs[idx];
        g_K[n0*256 + idx] = ks[idx];
        g_V[n0*256 + idx] = vs[idx];
    }
}

// ---------------- P2: kq, ck, pv (smem-staged weights, conflict-free) -------
__global__ void __launch_bounds__(256) kP2(const float* __restrict__ Wk_e,
                                           const float* __restrict__ Wq_e,
                                           const float* __restrict__ WOe)
{
    __shared__ float w_s[256][33];
    __shared__ float q8[8][DH_], k8[8][DH_], v8[8][DH_];
    const int n0 = blockIdx.x * 8;
    const int hh = blockIdx.y;
    const int t  = threadIdx.x;

    {
        const int n = t >> 5, k = t & 31;
        q8[n][k] = g_Q[((n0 + n)*H_ + hh)*DH_ + k];
        k8[n][k] = g_K[((n0 + n)*H_ + hh)*DH_ + k];
        v8[n][k] = g_V[((n0 + n)*H_ + hh)*DH_ + k];
    }
    for (int idx = t; idx < 8192; idx += 256)
        w_s[idx >> 5][idx & 31] = Wk_e[hh*8192 + idx];
    __syncthreads();

    float akq[8], apv[8];
    #pragma unroll
    for (int n = 0; n < 8; n++) { akq[n] = 0.f; apv[n] = 0.f; }
    #pragma unroll 4
    for (int k = 0; k < DH_; k++) {
        const float wk = w_s[t][k];
        const float wo = WOe[(hh*DH_ + k)*D_ + t];
        #pragma unroll
        for (int n = 0; n < 8; n++) { akq[n] += wk * q8[n][k]; apv[n] += wo * v8[n][k]; }
    }
    __syncthreads();
    for (int idx = t; idx < 8192; idx += 256)
        w_s[idx >> 5][idx & 31] = Wq_e[hh*8192 + idx];
    __syncthreads();

    float ack[8];
    #pragma unroll
    for (int n = 0; n < 8; n++) ack[n] = 0.f;
    #pragma unroll 4
    for (int k = 0; k < DH_; k++) {
        const float wq = w_s[t][k];
        #pragma unroll
        for (int n = 0; n < 8; n++) ack[n] += wq * k8[n][k];
    }
    #pragma unroll
    for (int n = 0; n < 8; n++) {
        const int base = ((n0 + n)*H_ + hh)*D_ + t;
        g_KQ[base] = akq[n] * SCALE_;
        g_CK[base] = ack[n] * SCALE_;
        g_PV[base] = apv[n];
    }
}

// ---------------- S: row pass (R12 phase-1) + we + x projections ------------
// Block = row i, 384 threads, thread = edge j. Phase 1: dots/p/si (exact R12).
// Phase 3: we accumulation re-reading the row (L2-resident). Phase 4: x_out.
__global__ void __launch_bounds__(384) kS(const float* __restrict__ e,
                                          const float* __restrict__ Wv_e,
                                          const float* __restrict__ bv_e,
                                          const float* __restrict__ WOx,
                                          const float* __restrict__ bOx,
                                          float* __restrict__ xout)
{
    __shared__ u64 kq2[H_][D_/2];    // broadcast operands (8 KB)
    __shared__ u64 ck2[H_][D_/2];    // 8 KB
    __shared__ float cbs[H_], sbs[H_], ls_s[H_];
    __shared__ __align__(16) float p_s[N_][H_];   // 12 KB
    __shared__ float we_s[H_][D_];                // 8 KB
    __shared__ float xh_s[D_];
    const int i = blockIdx.x;
    const int t = threadIdx.x;

    {
        const u64* kqsrc = (const u64*)(g_KQ + i*H_*D_);
        const u64* cksrc = (const u64*)(g_CK + i*H_*D_);
        u64* kqd = (u64*)kq2;  u64* ckd = (u64*)ck2;
        for (int idx = t; idx < H_*D_/2; idx += 384) { kqd[idx] = kqsrc[idx]; ckd[idx] = cksrc[idx]; }
    }
    if (t < H_) { cbs[t] = g_CB[i*H_ + t]; sbs[t] = g_SB[i*H_ + t]; ls_s[t] = 0.f; }
    __syncthreads();

    // ---- phase 1: per-edge dots (thread t = edge j = t) --------------------
    u64 aq[H_], as[H_];
    #pragma unroll
    for (int h = 0; h < H_; h++) { aq[h] = 0ull; as[h] = 0ull; }

    const float* ebase = e + (size_t)i*N_*D_;
    const float4* ep = (const float4*)(ebase + (size_t)t*D_);
    #pragma unroll 2
    for (int c = 0; c < 64; c++) {
        const float4 ev = ep[c];
        const u64 e0 = pack2f(ev.x, ev.y), e1 = pack2f(ev.z, ev.w);
        #pragma unroll
        for (int h = 0; h < H_; h++) {
            dfma2(aq[h], e0, kq2[h][2*c]); dfma2(aq[h], e1, kq2[h][2*c + 1]);
            dfma2(as[h], e0, ck2[h][2*c]); dfma2(as[h], e1, ck2[h][2*c + 1]);
        }
    }

    float si[H_], pv[H_];
    #pragma unroll
    for (int h = 0; h < H_; h++) {
        si[h] = hsum2(as[h]) + sbs[h];
        // scores O(+-5): exp2 cannot overflow; softmax shift-invariant.
        pv[h] = exp2f((hsum2(aq[h]) + cbs[h]) * L2E_);
    }
    float4* sip = (float4*)(g_SI + ((size_t)i*N_ + t)*H_);
    sip[0] = make_float4(si[0], si[1], si[2], si[3]);
    sip[1] = make_float4(si[4], si[5], si[6], si[7]);
    *(float4*)&p_s[t][0] = make_float4(pv[0], pv[1], pv[2], pv[3]);
    *(float4*)&p_s[t][4] = make_float4(pv[4], pv[5], pv[6], pv[7]);

    // lsum: butterfly once, then smem atomic
    #pragma unroll
    for (int h = 0; h < H_; h++) {
        float v = pv[h];
        #pragma unroll
        for (int o = 16; o; o >>= 1) v += __shfl_xor_sync(0xffffffffu, v, o);
        pv[h] = v;
    }
    const int l = t & 31;
    if (l < H_) atomicAdd(&ls_s[l], pv[l]);
    __syncthreads();

    // ---- phase 3: we[h][ch] = sum_j p[j][h]*e[i][j][ch]  (row re-read: L2) --
    if (t < D_) {
        float we[8];
        #pragma unroll
        for (int h = 0; h < 8; h++) we[h] = 0.f;
        const float* erow = ebase + t;
        #pragma unroll 4
        for (int j = 0; j < N_; j++) {
            const float ev = erow[(size_t)j*D_];
            const float4 pA = *(const float4*)&p_s[j][0];
            const float4 pB = *(const float4*)&p_s[j][4];
            we[0] += pA.x*ev; we[1] += pA.y*ev; we[2] += pA.z*ev; we[3] += pA.w*ev;
            we[4] += pB.x*ev; we[5] += pB.y*ev; we[6] += pB.z*ev; we[7] += pB.w*ev;
        }
        #pragma unroll
        for (int h = 0; h < 8; h++)
            we_s[h][t] = we[h] * __fdividef(1.f, ls_s[h]);
    }
    __syncthreads();

    // ---- phase 4: x projections --------------------------------------------
    if (t < D_) {
        const int h = t >> 5, k = t & 31;
        float acc = bv_e[h*DH_ + k];
        #pragma unroll 4
        for (int d = 0; d < D_; d++)
            acc += we_s[h][d] * Wv_e[(h*D_ + d)*DH_ + k];
        xh_s[t] = acc;
    }
    __syncthreads();
    if (t < D_) {
        float o = bOx[t];
        #pragma unroll 4
        for (int u = 0; u < D_; u++)
            o += xh_s[u] * WOx[u*D_ + t];
        xout[i*D_ + t] = o;
    }
}

// ---------------- T: column dots -- s_j, 2-way softmax -> ai/aj (R12) -------
// Block = col j, 384 threads, thread = i. Writes transposed [j][i][h].
__global__ void __launch_bounds__(384) kT(const float* __restrict__ e)
{
    __shared__ u64 ck2[H_][D_/2];
    __shared__ float sbs[H_];
    const int j = blockIdx.x;
    const int t = threadIdx.x;            // = i

    {
        const u64* cksrc = (const u64*)(g_CK + j*H_*D_);
        u64* ckd = (u64*)ck2;
        for (int idx = t; idx < H_*D_/2; idx += 384) ckd[idx] = cksrc[idx];
    }
    if (t < H_) sbs[t] = g_SB[j*H_ + t];
    __syncthreads();

    u64 as[H_];
    #pragma unroll
    for (int h = 0; h < H_; h++) as[h] = 0ull;

    const float4* ep = (const float4*)(e + ((size_t)t*N_ + j)*D_);
    #pragma unroll 2
    for (int c = 0; c < 64; c++) {
        const float4 ev = ep[c];
        const u64 e0 = pack2f(ev.x, ev.y), e1 = pack2f(ev.z, ev.w);
        #pragma unroll
        for (int h = 0; h < H_; h++) {
            dfma2(as[h], e0, ck2[h][2*c]); dfma2(as[h], e1, ck2[h][2*c + 1]);
        }
    }

    const float4 siA = *(const float4*)(g_SI + ((size_t)t*N_ + j)*H_);
    const float4 siB = *(const float4*)(g_SI + ((size_t)t*N_ + j)*H_ + 4);
    const float si[8] = {siA.x, siA.y, siA.z, siA.w, siB.x, siB.y, siB.z, siB.w};

    float ai[H_], aj[H_];
    #pragma unroll
    for (int h = 0; h < H_; h++) {
        // ai = 1/(1+exp(sj-si)); aj = 1-ai (sigmoid form of 2-way softmax)
        const float xv = exp2f((hsum2(as[h]) + sbs[h] - si[h]) * L2E_);
        ai[h] = __fdividef(1.f, 1.f + xv);
        aj[h] = 1.f - ai[h];
    }
    float4* aip = (float4*)(g_AI + ((size_t)j*N_ + t)*H_);
    aip[0] = make_float4(ai[0], ai[1], ai[2], ai[3]);
    aip[1] = make_float4(ai[4], ai[5], ai[6], ai[7]);
    float4* ajp = (float4*)(g_AJ + ((size_t)j*N_ + t)*H_);
    ajp[0] = make_float4(aj[0], aj[1], aj[2], aj[3]);
    ajp[1] = make_float4(aj[4], aj[5], aj[6], aj[7]);
}

// ---------------- E: eout = sum_h ai*pv_i + aj*pv_j + bOe -------------------
__global__ void __launch_bounds__(256) kE(const float* __restrict__ bOe,
                                          float* __restrict__ eout)
{
    const int i0 = blockIdx.x * 8;
    const int t  = threadIdx.x;
    const int tt = t & 127, ih = t >> 7;
    const int cp = 2 * tt;

    u64 pvi[4][H_];
    #pragma unroll
    for (int q = 0; q < 4; q++)
        #pragma unroll
        for (int h = 0; h < H_; h++)
            pvi[q][h] = *(const u64*)(g_PV + ((size_t)(i0 + ih*4 + q)*H_ + h)*D_ + cp);
    const u64 bo = *(const u64*)(bOe + cp);

    const int j0 = blockIdx.y * 48;
    for (int j = j0; j < j0 + 48; j++) {
        u64 pvj[H_];
        #pragma unroll
        for (int h = 0; h < H_; h++)
            pvj[h] = *(const u64*)(g_PV + ((size_t)j*H_ + h)*D_ + cp);
        #pragma unroll
        for (int q = 0; q < 4; q++) {
            const int irow = i0 + ih*4 + q;
            const float4 aiA = *(const float4*)(g_AI + ((size_t)j*N_ + irow)*H_);
            const float4 aiB = *(const float4*)(g_AI + ((size_t)j*N_ + irow)*H_ + 4);
            const float4 ajA = *(const float4*)(g_AJ + ((size_t)j*N_ + irow)*H_);
            const float4 ajB = *(const float4*)(g_AJ + ((size_t)j*N_ + irow)*H_ + 4);
            const float ai8[8] = {aiA.x, aiA.y, aiA.z, aiA.w, aiB.x, aiB.y, aiB.z, aiB.w};
            const float aj8[8] = {ajA.x, ajA.y, ajA.z, ajA.w, ajB.x, ajB.y, ajB.z, ajB.w};
            u64 acc = bo;
            #pragma unroll
            for (int h = 0; h < H_; h++) {
                dfma2(acc, bcast2(ai8[h]), pvi[q][h]);
                dfma2(acc, bcast2(aj8[h]), pvj[h]);
            }
            *(u64*)(eout + ((size_t)irow*N_ + j)*D_ + cp) = acc;
        }
    }
}

// ---------------- launcher ---------------------------------------------------
extern "C" void kernel_launch(void* const* d_in, const int* in_sizes, int n_in,
                              void* d_out, int out_size)
{
    const float* x    = (const float*)d_in[0];
    const float* e    = (const float*)d_in[1];
    const float* Wq_x = (const float*)d_in[2];
    const float* bq_x = (const float*)d_in[3];
    const float* Wk_e = (const float*)d_in[4];
    const float* bk_e = (const float*)d_in[5];
    const float* Wv_e = (const float*)d_in[6];
    const float* bv_e = (const float*)d_in[7];
    const float* Wq_e = (const float*)d_in[8];
    const float* bq_e = (const float*)d_in[9];
    const float* Wk_x = (const float*)d_in[10];
    const float* bk_x = (const float*)d_in[11];
    const float* Wv_x = (const float*)d_in[12];
    const float* bv_x = (const float*)d_in[13];
    const float* WOx  = (const float*)d_in[14];
    const float* bOx  = (const float*)d_in[15];
    const float* WOe  = (const float*)d_in[16];
    const float* bOe  = (const float*)d_in[17];

    float* xout = (float*)d_out;                 // [384,256]
    float* eout = (float*)d_out + N_*D_;         // [384,384,256]

    kP1<<<48, 256>>>(x, Wq_x, bq_x, Wk_x, bk_x, Wv_x, bv_x, bk_e, bq_e);
    kP2<<<dim3(48, 8), 256>>>(Wk_e, Wq_e, WOe);
    kS <<<N_, 384>>>(e, Wv_e, bv_e, WOx, bOx, xout);
    kT <<<N_, 384>>>(e);
    kE <<<dim3(48, 8), 256>>>(bOe, eout);
}